// round 3
// baseline (speedup 1.0000x reference)
#include <cuda_runtime.h>

// Problem constants
#define BATCH 32
#define IMG_H 480
#define IMG_W 640
#define OUT_H 470
#define OUT_W 630
#define WS    11

// Tiling
#define TILE_W 64
#define TILE_H 32
#define IN_W   (TILE_W + WS - 1)   // 74
#define IN_W_PAD 76                // pairs per row (pad for alignment)
#define IN_H   (TILE_H + WS - 1)   // 42
#define MID_W  TILE_W              // 64

#define GX 10   // ceil(630/64)
#define GY 15   // ceil(470/32)
#define NBLOCKS (GX * GY * BATCH)  // 4800
#define NTHREADS 256

typedef unsigned long long ull;

// Normalized 1D Gaussian, sigma=1.5, ws=11 (symmetric)
static __device__ __forceinline__ float gw(int t) {
    constexpr float w[11] = {
        0.00102839f, 0.00759866f, 0.03600077f, 0.10936124f, 0.21300553f,
        0.26601172f,
        0.21300553f, 0.10936124f, 0.03600077f, 0.00759866f, 0.00102839f
    };
    return w[t];
}
// packed (w, w) as b64 — constant-folded by ptxas (compile-time literal)
static __device__ __forceinline__ ull gw2(int t) {
    unsigned u = __float_as_uint(gw(t));
    return (((ull)u) << 32) | (ull)u;
}

// Packed f32x2 ops (sm_103a; ptxas never auto-fuses these — SASS_QUICKREF)
#define FMA2(d, a, b, c) \
    asm("fma.rn.f32x2 %0, %1, %2, %3;" : "=l"(d) : "l"(a), "l"(b), "l"(c))
#define MUL2(d, a, b) \
    asm("mul.rn.f32x2 %0, %1, %2;" : "=l"(d) : "l"(a), "l"(b))
#define UNPK(lo, hi, p) \
    asm("mov.b64 {%0, %1}, %2;" : "=r"(lo), "=r"(hi) : "l"(p))

union F4U { float4 v; ull u[2]; };

__device__ float        g_partials[NBLOCKS];
__device__ unsigned int g_count = 0;

__global__ __launch_bounds__(NTHREADS, 2)
void ssim_tile_kernel(const float* __restrict__ img1,
                      const float* __restrict__ img2,
                      float* __restrict__ out)
{
    extern __shared__ float smem[];
    // layout: [pairs (x,y)] [mid AB float4 (mu-pair, sq-pair)] [mid xy scalar]
    float2* s_xy   = (float2*)smem;                                   // IN_H * IN_W_PAD pairs
    float4* s_mab  = (float4*)(smem + 2 * IN_H * IN_W_PAD);           // IN_H * MID_W
    float*  s_mc   = (float*)(s_mab + IN_H * MID_W);                  // IN_H * MID_W

    __shared__ float    s_red[NTHREADS / 32];
    __shared__ unsigned s_flag;

    const int tid = threadIdx.x;
    const int bz  = blockIdx.z;
    const int r0  = blockIdx.y * TILE_H;
    const int c0  = blockIdx.x * TILE_W;

    const float* im1 = img1 + (size_t)bz * IMG_H * IMG_W;
    const float* im2 = img2 + (size_t)bz * IMG_H * IMG_W;

    // ---- Stage 1: load input tile (halo), interleaved (x,y) pairs ----
    for (int i = tid; i < IN_H * IN_W; i += NTHREADS) {
        int r = i / IN_W;
        int c = i - r * IN_W;
        int gr = r0 + r;
        int gc = c0 + c;
        float v1 = 0.f, v2 = 0.f;
        if (gr < IMG_H && gc < IMG_W) {
            int idx = gr * IMG_W + gc;
            v1 = im1[idx];
            v2 = im2[idx];
        }
        s_xy[r * IN_W_PAD + c] = make_float2(v1, v2);
    }
    __syncthreads();

    // ---- Stage 2: horizontal conv, packed channels, 4-wide strips ----
    for (int s = tid; s < IN_H * (TILE_W / 4); s += NTHREADS) {
        int row = s >> 4;
        int cq  = (s & 15) << 2;

        // 7 x LDS.128 = 14 packed (x,y) pairs
        const float4* bp = (const float4*)(s_xy + row * IN_W_PAD + cq);
        ull p[14];
        #pragma unroll
        for (int i = 0; i < 7; i++) {
            F4U u; u.v = bp[i];
            p[2 * i]     = u.u[0];
            p[2 * i + 1] = u.u[1];
        }

        ull   am[4] = {0, 0, 0, 0};   // packed (mu1, mu2)
        ull   as_[4] = {0, 0, 0, 0};  // packed (Exx, Eyy)
        float axy[4] = {0.f, 0.f, 0.f, 0.f};

        #pragma unroll
        for (int k = 0; k < WS + 3; k++) {
            ull pk = p[k];
            unsigned ulo, uhi;
            UNPK(ulo, uhi, pk);
            float xy = __uint_as_float(ulo) * __uint_as_float(uhi);
            ull sq;
            MUL2(sq, pk, pk);
            #pragma unroll
            for (int o = 0; o < 4; o++) {
                int t = k - o;
                if (t >= 0 && t < WS) {     // compile-time resolved (fully unrolled)
                    ull w2 = gw2(t);
                    FMA2(am[o],  w2, pk, am[o]);
                    FMA2(as_[o], w2, sq, as_[o]);
                    axy[o] = fmaf(gw(t), xy, axy[o]);
                }
            }
        }

        float4* mrow = s_mab + row * MID_W + cq;
        float*  crow = s_mc  + row * MID_W + cq;
        #pragma unroll
        for (int o = 0; o < 4; o++) {
            F4U u; u.u[0] = am[o]; u.u[1] = as_[o];
            mrow[o] = u.v;          // STS.128
            crow[o] = axy[o];       // STS.32
        }
    }
    __syncthreads();

    // ---- Stage 3: vertical conv (packed) + SSIM + local sum, 4-tall ----
    const float C1 = 1.0f;   // (0.01*100)^2
    const float C2 = 9.0f;   // (0.03*100)^2
    float lsum = 0.f;

    for (int s = tid; s < (TILE_H / 4) * TILE_W; s += NTHREADS) {
        int c  = s & (TILE_W - 1);
        int rq = (s >> 6) << 2;

        ull   am[4] = {0, 0, 0, 0};
        ull   as_[4] = {0, 0, 0, 0};
        float axy[4] = {0.f, 0.f, 0.f, 0.f};

        #pragma unroll
        for (int k = 0; k < WS + 3; k++) {
            int row = rq + k;
            F4U u; u.v = s_mab[row * MID_W + c];   // LDS.128
            ull pm = u.u[0];
            ull ps = u.u[1];
            float pc = s_mc[row * MID_W + c];      // LDS.32
            #pragma unroll
            for (int o = 0; o < 4; o++) {
                int t = k - o;
                if (t >= 0 && t < WS) {
                    ull w2 = gw2(t);
                    FMA2(am[o],  w2, pm, am[o]);
                    FMA2(as_[o], w2, ps, as_[o]);
                    axy[o] = fmaf(gw(t), pc, axy[o]);
                }
            }
        }

        int gc = c0 + c;
        if (gc < OUT_W) {
            #pragma unroll
            for (int o = 0; o < 4; o++) {
                int gr = r0 + rq + o;
                if (gr < OUT_H) {
                    unsigned u1, u2, ux, uy;
                    UNPK(u1, u2, am[o]);
                    UNPK(ux, uy, as_[o]);
                    float mu1 = __uint_as_float(u1);
                    float mu2 = __uint_as_float(u2);
                    float Exx = __uint_as_float(ux);
                    float Eyy = __uint_as_float(uy);
                    float Exy = axy[o];
                    float mu1sq = mu1 * mu1;
                    float mu2sq = mu2 * mu2;
                    float mu12  = mu1 * mu2;
                    float s1  = Exx - mu1sq;
                    float s2  = Eyy - mu2sq;
                    float s12 = Exy - mu12;
                    float v1 = 2.f * s12 + C2;
                    float v2 = s1 + s2 + C2;
                    float num = (2.f * mu12 + C1) * v1;
                    float den = (mu1sq + mu2sq + C1) * v2;
                    lsum += __fdividef(num, den);
                }
            }
        }
    }

    // ---- Stage 4: block partial + fused last-block finalize ----
    #pragma unroll
    for (int off = 16; off > 0; off >>= 1)
        lsum += __shfl_down_sync(0xffffffffu, lsum, off);

    int warp = tid >> 5;
    int lane = tid & 31;
    if (lane == 0) s_red[warp] = lsum;
    __syncthreads();
    if (tid == 0) {
        float t = 0.f;
        #pragma unroll
        for (int i = 0; i < NTHREADS / 32; i++) t += s_red[i];
        int bidx = (blockIdx.z * GY + blockIdx.y) * GX + blockIdx.x;
        g_partials[bidx] = t;
        __threadfence();
        unsigned v = atomicAdd(&g_count, 1u);
        s_flag = (v == (unsigned)(NBLOCKS - 1));
    }
    __syncthreads();

    if (s_flag) {
        // deterministic: fixed summation order independent of which block runs this
        float acc = 0.f;
        for (int i = tid; i < NBLOCKS; i += NTHREADS)
            acc += __ldcg(&g_partials[i]);
        #pragma unroll
        for (int off = 16; off > 0; off >>= 1)
            acc += __shfl_down_sync(0xffffffffu, acc, off);
        if (lane == 0) s_red[warp] = acc;
        __syncthreads();
        if (tid == 0) {
            float tt = 0.f;
            #pragma unroll
            for (int i = 0; i < NTHREADS / 32; i++) tt += s_red[i];
            float mean = tt * (1.0f / ((float)BATCH * OUT_H * OUT_W));
            out[0] = (1.0f - mean) * 0.5f;
            g_count = 0;   // reset for next graph replay
        }
    }
}

extern "C" void kernel_launch(void* const* d_in, const int* in_sizes, int n_in,
                              void* d_out, int out_size)
{
    const float* img1 = (const float*)d_in[0];
    const float* img2 = (const float*)d_in[1];
    float* out = (float*)d_out;

    size_t smem_bytes = (size_t)(2 * IN_H * IN_W_PAD) * sizeof(float)   // pairs
                      + (size_t)(IN_H * MID_W) * sizeof(float4)          // mid AB
                      + (size_t)(IN_H * MID_W) * sizeof(float);          // mid xy
    cudaFuncSetAttribute(ssim_tile_kernel,
                         cudaFuncAttributeMaxDynamicSharedMemorySize,
                         (int)smem_bytes);

    dim3 grid(GX, GY, BATCH);
    ssim_tile_kernel<<<grid, NTHREADS, smem_bytes>>>(img1, img2, out);
}

// round 4
// speedup vs baseline: 1.3432x; 1.3432x over previous
#include <cuda_runtime.h>

// Problem constants
#define BATCH 32
#define IMG_H 480
#define IMG_W 640
#define OUT_H 470
#define OUT_W 630
#define WS    11

// Tiling
#define TILE_W 64
#define TILE_H 32
#define IN_W   (TILE_W + WS - 1)   // 74
#define IN_W_PAD 76                // multiple of 4 for float4 loads
#define IN_H   (TILE_H + WS - 1)   // 42
#define MID_W  TILE_W              // 64

#define GX 10   // ceil(630/64)
#define GY 15   // ceil(470/32)
#define NBLOCKS (GX * GY * BATCH)  // 4800
#define NTHREADS 512

// Normalized 1D Gaussian, sigma=1.5, ws=11 (symmetric)
static __device__ __forceinline__ float gw(int t) {
    constexpr float w[11] = {
        0.00102839f, 0.00759866f, 0.03600077f, 0.10936124f, 0.21300553f,
        0.26601172f,
        0.21300553f, 0.10936124f, 0.03600077f, 0.00759866f, 0.00102839f
    };
    return w[t];
}

__device__ float        g_partials[NBLOCKS];
__device__ unsigned int g_count = 0;

__global__ __launch_bounds__(NTHREADS, 2)
void ssim_tile_kernel(const float* __restrict__ img1,
                      const float* __restrict__ img2,
                      float* __restrict__ out)
{
    extern __shared__ float smem[];
    float* s_x   = smem;                          // IN_H * IN_W_PAD
    float* s_y   = s_x + IN_H * IN_W_PAD;         // IN_H * IN_W_PAD
    float* s_mid = s_y + IN_H * IN_W_PAD;         // 5 * IN_H * MID_W (SoA, conflict-free)

    __shared__ float    s_red[NTHREADS / 32];
    __shared__ unsigned s_flag;

    const int tid = threadIdx.x;
    const int bz  = blockIdx.z;
    const int r0  = blockIdx.y * TILE_H;
    const int c0  = blockIdx.x * TILE_W;

    const float* im1 = img1 + (size_t)bz * IMG_H * IMG_W;
    const float* im2 = img2 + (size_t)bz * IMG_H * IMG_W;

    // ---- Stage 1: load input tile (with halo), OOB -> 0 ----
    for (int i = tid; i < IN_H * IN_W; i += NTHREADS) {
        int r = i / IN_W;
        int c = i - r * IN_W;
        int gr = r0 + r;
        int gc = c0 + c;
        float v1 = 0.f, v2 = 0.f;
        if (gr < IMG_H && gc < IMG_W) {
            int idx = gr * IMG_W + gc;
            v1 = im1[idx];
            v2 = im2[idx];
        }
        s_x[r * IN_W_PAD + c] = v1;
        s_y[r * IN_W_PAD + c] = v2;
    }
    __syncthreads();

    // ---- Stage 2: horizontal conv, 5 channels, 4-wide strips ----
    // float4 smem loads (aligned: cq multiple of 4, IN_W_PAD multiple of 4);
    // products computed on-the-fly so only x,y are read.
    for (int s = tid; s < IN_H * (TILE_W / 4); s += NTHREADS) {
        int row = s >> 4;            // s / 16
        int cq  = (s & 15) << 2;     // (s % 16) * 4

        const float4* px4 = (const float4*)(s_x + row * IN_W_PAD + cq);
        const float4* py4 = (const float4*)(s_y + row * IN_W_PAD + cq);
        float xs[16], ys[16];
        #pragma unroll
        for (int i = 0; i < 4; i++) {
            float4 vx = px4[i];
            float4 vy = py4[i];
            xs[4*i+0] = vx.x; xs[4*i+1] = vx.y; xs[4*i+2] = vx.z; xs[4*i+3] = vx.w;
            ys[4*i+0] = vy.x; ys[4*i+1] = vy.y; ys[4*i+2] = vy.z; ys[4*i+3] = vy.w;
        }

        float a0[4] = {0.f, 0.f, 0.f, 0.f};  // mu1
        float a1[4] = {0.f, 0.f, 0.f, 0.f};  // mu2
        float a2[4] = {0.f, 0.f, 0.f, 0.f};  // xx
        float a3[4] = {0.f, 0.f, 0.f, 0.f};  // yy
        float a4[4] = {0.f, 0.f, 0.f, 0.f};  // xy

        #pragma unroll
        for (int k = 0; k < WS + 3; k++) {   // 14 taps serve 4 outputs
            float xv = xs[k];
            float yv = ys[k];
            float xx = xv * xv;
            float yy = yv * yv;
            float xy = xv * yv;
            #pragma unroll
            for (int o = 0; o < 4; o++) {
                int t = k - o;
                if (t >= 0 && t < WS) {      // compile-time resolved
                    float w = gw(t);         // literal -> FFMA-imm (rt=1)
                    a0[o] = fmaf(w, xv, a0[o]);
                    a1[o] = fmaf(w, yv, a1[o]);
                    a2[o] = fmaf(w, xx, a2[o]);
                    a3[o] = fmaf(w, yy, a3[o]);
                    a4[o] = fmaf(w, xy, a4[o]);
                }
            }
        }
        float* m = s_mid + row * MID_W + cq;
        #pragma unroll
        for (int o = 0; o < 4; o++) {
            m[0 * IN_H * MID_W + o] = a0[o];
            m[1 * IN_H * MID_W + o] = a1[o];
            m[2 * IN_H * MID_W + o] = a2[o];
            m[3 * IN_H * MID_W + o] = a3[o];
            m[4 * IN_H * MID_W + o] = a4[o];
        }
    }
    __syncthreads();

    // ---- Stage 3: vertical conv + SSIM + local sum, 4-tall strips ----
    // (TILE_H/4)*TILE_W = 512 strips == NTHREADS: exactly one per thread.
    const float C1 = 1.0f;   // (0.01*100)^2
    const float C2 = 9.0f;   // (0.03*100)^2
    float lsum = 0.f;

    {
        int s  = tid;
        int c  = s & (TILE_W - 1);
        int rq = (s >> 6) << 2;

        float m1[4]  = {0.f, 0.f, 0.f, 0.f};
        float m2[4]  = {0.f, 0.f, 0.f, 0.f};
        float exx[4] = {0.f, 0.f, 0.f, 0.f};
        float eyy[4] = {0.f, 0.f, 0.f, 0.f};
        float exy[4] = {0.f, 0.f, 0.f, 0.f};

        #pragma unroll
        for (int k = 0; k < WS + 3; k++) {
            int row = rq + k;
            const float* m = s_mid + row * MID_W + c;
            float v0 = m[0 * IN_H * MID_W];
            float v1 = m[1 * IN_H * MID_W];
            float v2 = m[2 * IN_H * MID_W];
            float v3 = m[3 * IN_H * MID_W];
            float v4 = m[4 * IN_H * MID_W];
            #pragma unroll
            for (int o = 0; o < 4; o++) {
                int t = k - o;
                if (t >= 0 && t < WS) {
                    float w = gw(t);
                    m1[o]  = fmaf(w, v0, m1[o]);
                    m2[o]  = fmaf(w, v1, m2[o]);
                    exx[o] = fmaf(w, v2, exx[o]);
                    eyy[o] = fmaf(w, v3, eyy[o]);
                    exy[o] = fmaf(w, v4, exy[o]);
                }
            }
        }

        int gc = c0 + c;
        if (gc < OUT_W) {
            #pragma unroll
            for (int o = 0; o < 4; o++) {
                int gr = r0 + rq + o;
                if (gr < OUT_H) {
                    float mu1 = m1[o], mu2 = m2[o];
                    float mu1sq = mu1 * mu1;
                    float mu2sq = mu2 * mu2;
                    float mu12  = mu1 * mu2;
                    float s1  = exx[o] - mu1sq;
                    float s2  = eyy[o] - mu2sq;
                    float s12 = exy[o] - mu12;
                    float v1 = 2.f * s12 + C2;
                    float v2 = s1 + s2 + C2;
                    float num = (2.f * mu12 + C1) * v1;
                    float den = (mu1sq + mu2sq + C1) * v2;
                    lsum += __fdividef(num, den);
                }
            }
        }
    }

    // ---- Stage 4: block partial + fused last-block finalize ----
    #pragma unroll
    for (int off = 16; off > 0; off >>= 1)
        lsum += __shfl_down_sync(0xffffffffu, lsum, off);

    int warp = tid >> 5;
    int lane = tid & 31;
    if (lane == 0) s_red[warp] = lsum;
    __syncthreads();
    if (tid == 0) {
        float t = 0.f;
        #pragma unroll
        for (int i = 0; i < NTHREADS / 32; i++) t += s_red[i];
        int bidx = (blockIdx.z * GY + blockIdx.y) * GX + blockIdx.x;
        g_partials[bidx] = t;
        __threadfence();
        unsigned v = atomicAdd(&g_count, 1u);
        s_flag = (v == (unsigned)(NBLOCKS - 1));
    }
    __syncthreads();

    if (s_flag) {
        // deterministic: fixed summation order independent of which block runs this
        float acc = 0.f;
        for (int i = tid; i < NBLOCKS; i += NTHREADS)
            acc += __ldcg(&g_partials[i]);
        #pragma unroll
        for (int off = 16; off > 0; off >>= 1)
            acc += __shfl_down_sync(0xffffffffu, acc, off);
        if (lane == 0) s_red[warp] = acc;
        __syncthreads();
        if (tid == 0) {
            float tt = 0.f;
            #pragma unroll
            for (int i = 0; i < NTHREADS / 32; i++) tt += s_red[i];
            float mean = tt * (1.0f / ((float)BATCH * OUT_H * OUT_W));
            out[0] = (1.0f - mean) * 0.5f;
            g_count = 0;   // reset for next graph replay
        }
    }
}

extern "C" void kernel_launch(void* const* d_in, const int* in_sizes, int n_in,
                              void* d_out, int out_size)
{
    const float* img1 = (const float*)d_in[0];
    const float* img2 = (const float*)d_in[1];
    float* out = (float*)d_out;

    size_t smem_bytes = (size_t)(2 * IN_H * IN_W_PAD + 5 * IN_H * MID_W) * sizeof(float);
    cudaFuncSetAttribute(ssim_tile_kernel,
                         cudaFuncAttributeMaxDynamicSharedMemorySize,
                         (int)smem_bytes);

    dim3 grid(GX, GY, BATCH);
    ssim_tile_kernel<<<grid, NTHREADS, smem_bytes>>>(img1, img2, out);
}

// round 5
// speedup vs baseline: 1.5197x; 1.1314x over previous
#include <cuda_runtime.h>

// Problem constants
#define BATCH 32
#define IMG_H 480
#define IMG_W 640
#define OUT_H 470
#define OUT_W 630
#define WS    11

// Tiling: 32 wide x 64 tall
#define TILE_W 32
#define TILE_H 64
#define IN_W   (TILE_W + WS - 1)   // 42
#define IN_W_PAD 44                // multiple of 4 for float4 loads
#define IN_H   (TILE_H + WS - 1)   // 74
#define MID_W  TILE_W              // 32

#define GX 20   // ceil(630/32)
#define GY 8    // ceil(470/64)
#define NBLOCKS (GX * GY * BATCH)  // 5120
#define NTHREADS 512

// Normalized 1D Gaussian, sigma=1.5, ws=11 (symmetric)
static __device__ __forceinline__ float gw(int t) {
    constexpr float w[11] = {
        0.00102839f, 0.00759866f, 0.03600077f, 0.10936124f, 0.21300553f,
        0.26601172f,
        0.21300553f, 0.10936124f, 0.03600077f, 0.00759866f, 0.00102839f
    };
    return w[t];
}

__device__ float        g_partials[NBLOCKS];
__device__ unsigned int g_count = 0;

__global__ __launch_bounds__(NTHREADS, 3)
void ssim_tile_kernel(const float* __restrict__ img1,
                      const float* __restrict__ img2,
                      float* __restrict__ out)
{
    extern __shared__ float smem[];
    float*  s_x   = smem;                                  // IN_H * IN_W_PAD
    float*  s_y   = s_x + IN_H * IN_W_PAD;                 // IN_H * IN_W_PAD
    float2* s_mAB = (float2*)(s_y + IN_H * IN_W_PAD);      // IN_H*MID_W  (mu1,mu2)
    float2* s_mCD = s_mAB + IN_H * MID_W;                  // IN_H*MID_W  (xx,yy)
    float*  s_mE  = (float*)(s_mCD + IN_H * MID_W);        // IN_H*MID_W  (xy)

    __shared__ float    s_red[NTHREADS / 32];
    __shared__ unsigned s_flag;

    const int tid = threadIdx.x;
    const int bz  = blockIdx.z;
    const int r0  = blockIdx.y * TILE_H;
    const int c0  = blockIdx.x * TILE_W;

    const float* im1 = img1 + (size_t)bz * IMG_H * IMG_W;
    const float* im2 = img2 + (size_t)bz * IMG_H * IMG_W;

    // ---- Stage 1: load input tile (with halo), OOB -> 0 ----
    for (int i = tid; i < IN_H * IN_W; i += NTHREADS) {
        int r = i / IN_W;
        int c = i - r * IN_W;
        int gr = r0 + r;
        int gc = c0 + c;
        float v1 = 0.f, v2 = 0.f;
        if (gr < IMG_H && gc < IMG_W) {
            int idx = gr * IMG_W + gc;
            v1 = im1[idx];
            v2 = im2[idx];
        }
        s_x[r * IN_W_PAD + c] = v1;
        s_y[r * IN_W_PAD + c] = v2;
    }
    __syncthreads();

    // ---- Stage 2: horizontal conv, 5 channels, 4-wide strips ----
    // 592 strips (74 rows x 8 quads); float4 smem loads (cq mult of 4).
    for (int s = tid; s < IN_H * (TILE_W / 4); s += NTHREADS) {
        int row = s >> 3;            // s / 8
        int cq  = (s & 7) << 2;      // (s % 8) * 4

        const float4* px4 = (const float4*)(s_x + row * IN_W_PAD + cq);
        const float4* py4 = (const float4*)(s_y + row * IN_W_PAD + cq);
        float xs[16], ys[16];
        #pragma unroll
        for (int i = 0; i < 4; i++) {
            float4 vx = px4[i];
            float4 vy = py4[i];
            xs[4*i+0] = vx.x; xs[4*i+1] = vx.y; xs[4*i+2] = vx.z; xs[4*i+3] = vx.w;
            ys[4*i+0] = vy.x; ys[4*i+1] = vy.y; ys[4*i+2] = vy.z; ys[4*i+3] = vy.w;
        }

        float a0[4] = {0.f, 0.f, 0.f, 0.f};  // mu1
        float a1[4] = {0.f, 0.f, 0.f, 0.f};  // mu2
        float a2[4] = {0.f, 0.f, 0.f, 0.f};  // xx
        float a3[4] = {0.f, 0.f, 0.f, 0.f};  // yy
        float a4[4] = {0.f, 0.f, 0.f, 0.f};  // xy

        #pragma unroll
        for (int k = 0; k < WS + 3; k++) {   // 14 taps serve 4 outputs
            float xv = xs[k];
            float yv = ys[k];
            float xx = xv * xv;
            float yy = yv * yv;
            float xy = xv * yv;
            #pragma unroll
            for (int o = 0; o < 4; o++) {
                int t = k - o;
                if (t >= 0 && t < WS) {      // compile-time resolved
                    float w = gw(t);         // literal -> FFMA-imm (rt=1)
                    a0[o] = fmaf(w, xv, a0[o]);
                    a1[o] = fmaf(w, yv, a1[o]);
                    a2[o] = fmaf(w, xx, a2[o]);
                    a3[o] = fmaf(w, yy, a3[o]);
                    a4[o] = fmaf(w, xy, a4[o]);
                }
            }
        }
        // vectorized stores: 5 x STS.128
        float4* ab4 = (float4*)(s_mAB + row * MID_W + cq);
        float4* cd4 = (float4*)(s_mCD + row * MID_W + cq);
        float4* e4  = (float4*)(s_mE  + row * MID_W + cq);
        ab4[0] = make_float4(a0[0], a1[0], a0[1], a1[1]);
        ab4[1] = make_float4(a0[2], a1[2], a0[3], a1[3]);
        cd4[0] = make_float4(a2[0], a3[0], a2[1], a3[1]);
        cd4[1] = make_float4(a2[2], a3[2], a2[3], a3[3]);
        e4[0]  = make_float4(a4[0], a4[1], a4[2], a4[3]);
    }
    __syncthreads();

    // ---- Stage 3: vertical conv + SSIM + local sum, 4-tall strips ----
    // (TILE_H/4)*TILE_W = 512 strips == NTHREADS: exactly one per thread.
    const float C1 = 1.0f;   // (0.01*100)^2
    const float C2 = 9.0f;   // (0.03*100)^2
    float lsum = 0.f;

    {
        int c  = tid & (TILE_W - 1);
        int rq = (tid >> 5) << 2;

        float m1[4]  = {0.f, 0.f, 0.f, 0.f};
        float m2[4]  = {0.f, 0.f, 0.f, 0.f};
        float exx[4] = {0.f, 0.f, 0.f, 0.f};
        float eyy[4] = {0.f, 0.f, 0.f, 0.f};
        float exy[4] = {0.f, 0.f, 0.f, 0.f};

        #pragma unroll
        for (int k = 0; k < WS + 3; k++) {
            int row = rq + k;
            float2 vab = s_mAB[row * MID_W + c];   // LDS.64
            float2 vcd = s_mCD[row * MID_W + c];   // LDS.64
            float  ve  = s_mE [row * MID_W + c];   // LDS.32
            #pragma unroll
            for (int o = 0; o < 4; o++) {
                int t = k - o;
                if (t >= 0 && t < WS) {
                    float w = gw(t);
                    m1[o]  = fmaf(w, vab.x, m1[o]);
                    m2[o]  = fmaf(w, vab.y, m2[o]);
                    exx[o] = fmaf(w, vcd.x, exx[o]);
                    eyy[o] = fmaf(w, vcd.y, eyy[o]);
                    exy[o] = fmaf(w, ve,    exy[o]);
                }
            }
        }

        int gc = c0 + c;
        if (gc < OUT_W) {
            #pragma unroll
            for (int o = 0; o < 4; o++) {
                int gr = r0 + rq + o;
                if (gr < OUT_H) {
                    float mu1 = m1[o], mu2 = m2[o];
                    float mu1sq = mu1 * mu1;
                    float mu2sq = mu2 * mu2;
                    float mu12  = mu1 * mu2;
                    float s1  = exx[o] - mu1sq;
                    float s2  = eyy[o] - mu2sq;
                    float s12 = exy[o] - mu12;
                    float v1 = 2.f * s12 + C2;
                    float v2 = s1 + s2 + C2;
                    float num = (2.f * mu12 + C1) * v1;
                    float den = (mu1sq + mu2sq + C1) * v2;
                    lsum += __fdividef(num, den);
                }
            }
        }
    }

    // ---- Stage 4: block partial + fused last-block finalize ----
    #pragma unroll
    for (int off = 16; off > 0; off >>= 1)
        lsum += __shfl_down_sync(0xffffffffu, lsum, off);

    int warp = tid >> 5;
    int lane = tid & 31;
    if (lane == 0) s_red[warp] = lsum;
    __syncthreads();
    if (tid == 0) {
        float t = 0.f;
        #pragma unroll
        for (int i = 0; i < NTHREADS / 32; i++) t += s_red[i];
        int bidx = (blockIdx.z * GY + blockIdx.y) * GX + blockIdx.x;
        g_partials[bidx] = t;
        __threadfence();
        unsigned v = atomicAdd(&g_count, 1u);
        s_flag = (v == (unsigned)(NBLOCKS - 1));
    }
    __syncthreads();

    if (s_flag) {
        // deterministic: fixed summation order independent of which block runs this
        float acc = 0.f;
        for (int i = tid; i < NBLOCKS; i += NTHREADS)
            acc += __ldcg(&g_partials[i]);
        #pragma unroll
        for (int off = 16; off > 0; off >>= 1)
            acc += __shfl_down_sync(0xffffffffu, acc, off);
        if (lane == 0) s_red[warp] = acc;
        __syncthreads();
        if (tid == 0) {
            float tt = 0.f;
            #pragma unroll
            for (int i = 0; i < NTHREADS / 32; i++) tt += s_red[i];
            float mean = tt * (1.0f / ((float)BATCH * OUT_H * OUT_W));
            out[0] = (1.0f - mean) * 0.5f;
            g_count = 0;   // reset for next graph replay
        }
    }
}

extern "C" void kernel_launch(void* const* d_in, const int* in_sizes, int n_in,
                              void* d_out, int out_size)
{
    const float* img1 = (const float*)d_in[0];
    const float* img2 = (const float*)d_in[1];
    float* out = (float*)d_out;

    size_t smem_bytes = (size_t)(2 * IN_H * IN_W_PAD + 5 * IN_H * MID_W) * sizeof(float);
    cudaFuncSetAttribute(ssim_tile_kernel,
                         cudaFuncAttributeMaxDynamicSharedMemorySize,
                         (int)smem_bytes);

    dim3 grid(GX, GY, BATCH);
    ssim_tile_kernel<<<grid, NTHREADS, smem_bytes>>>(img1, img2, out);
}

// round 8
// speedup vs baseline: 1.7301x; 1.1385x over previous
#include <cuda_runtime.h>

// Problem constants
#define BATCH 32
#define IMG_H 480
#define IMG_W 640
#define OUT_H 470
#define OUT_W 630
#define WS    11

// Tiling: 32 wide x 64 tall
#define TILE_W 32
#define TILE_H 64
#define IN_W   (TILE_W + WS - 1)   // 42
#define IN_W_PAD 44                // multiple of 4 for float4 loads
#define IN_H   (TILE_H + WS - 1)   // 74
#define MID_W  TILE_W              // 32

#define GX 20   // ceil(630/32)
#define GY 8    // ceil(470/64)
#define NBLOCKS (GX * GY * BATCH)  // 5120
#define NTHREADS 512

// Normalized 1D Gaussian, sigma=1.5, ws=11 (symmetric)
static __device__ __forceinline__ float gw(int t) {
    constexpr float w[11] = {
        0.00102839f, 0.00759866f, 0.03600077f, 0.10936124f, 0.21300553f,
        0.26601172f,
        0.21300553f, 0.10936124f, 0.03600077f, 0.00759866f, 0.00102839f
    };
    return w[t];
}

__device__ float        g_partials[NBLOCKS];
__device__ unsigned int g_count = 0;

__global__ __launch_bounds__(NTHREADS, 3)
void ssim_tile_kernel(const float* __restrict__ img1,
                      const float* __restrict__ img2,
                      float* __restrict__ out)
{
    extern __shared__ float smem[];
    float*  s_s   = smem;                                  // IN_H * IN_W_PAD  (x+y)
    float*  s_d   = s_s + IN_H * IN_W_PAD;                 // IN_H * IN_W_PAD  (x-y)
    float4* s_mid = (float4*)(s_d + IN_H * IN_W_PAD);      // IN_H * MID_W (Ms,Md,Es,Ed)

    __shared__ float    s_red[NTHREADS / 32];
    __shared__ unsigned s_flag;

    const int tid = threadIdx.x;
    const int bz  = blockIdx.z;
    const int r0  = blockIdx.y * TILE_H;
    const int c0  = blockIdx.x * TILE_W;

    const float* im1 = img1 + (size_t)bz * IMG_H * IMG_W;
    const float* im2 = img2 + (size_t)bz * IMG_H * IMG_W;

    // ---- Stage 1: load tile (with halo), store s=x+y, d=x-y ----
    if (c0 + IN_W_PAD <= IMG_W && r0 + IN_H <= IMG_H) {
        // fast path: interior block, float4 loads (row start 16B-aligned:
        // c0 multiple of 32, IMG_W multiple of 4)
        const int NQ = IN_W_PAD / 4;   // 11 quads per row
        for (int i = tid; i < IN_H * NQ; i += NTHREADS) {
            int r = i / NQ;
            int q = i - r * NQ;
            const float4* p1 = (const float4*)(im1 + (size_t)(r0 + r) * IMG_W + c0) + q;
            const float4* p2 = (const float4*)(im2 + (size_t)(r0 + r) * IMG_W + c0) + q;
            float4 a = *p1;
            float4 b = *p2;
            float4 sv = make_float4(a.x + b.x, a.y + b.y, a.z + b.z, a.w + b.w);
            float4 dv = make_float4(a.x - b.x, a.y - b.y, a.z - b.z, a.w - b.w);
            ((float4*)(s_s + r * IN_W_PAD))[q] = sv;
            ((float4*)(s_d + r * IN_W_PAD))[q] = dv;
        }
    } else {
        for (int i = tid; i < IN_H * IN_W_PAD; i += NTHREADS) {
            int r = i / IN_W_PAD;
            int c = i - r * IN_W_PAD;
            int gr = r0 + r;
            int gc = c0 + c;
            float v1 = 0.f, v2 = 0.f;
            if (gr < IMG_H && gc < IMG_W) {
                int idx = gr * IMG_W + gc;
                v1 = im1[idx];
                v2 = im2[idx];
            }
            s_s[r * IN_W_PAD + c] = v1 + v2;
            s_d[r * IN_W_PAD + c] = v1 - v2;
        }
    }
    __syncthreads();

    // ---- Stage 2: horizontal conv, 4 channels (s, d, s^2, d^2), 4-wide strips ----
    for (int st = tid; st < IN_H * (TILE_W / 4); st += NTHREADS) {
        int row = st >> 3;            // st / 8
        int cq  = (st & 7) << 2;      // (st % 8) * 4

        const float4* ps4 = (const float4*)(s_s + row * IN_W_PAD + cq);
        const float4* pd4 = (const float4*)(s_d + row * IN_W_PAD + cq);
        float sv[16], dv[16];
        #pragma unroll
        for (int i = 0; i < 4; i++) {
            float4 a = ps4[i];
            float4 b = pd4[i];
            sv[4*i+0] = a.x; sv[4*i+1] = a.y; sv[4*i+2] = a.z; sv[4*i+3] = a.w;
            dv[4*i+0] = b.x; dv[4*i+1] = b.y; dv[4*i+2] = b.z; dv[4*i+3] = b.w;
        }

        float aMs[4] = {0.f, 0.f, 0.f, 0.f};
        float aMd[4] = {0.f, 0.f, 0.f, 0.f};
        float aEs[4] = {0.f, 0.f, 0.f, 0.f};
        float aEd[4] = {0.f, 0.f, 0.f, 0.f};

        #pragma unroll
        for (int k = 0; k < WS + 3; k++) {   // 14 taps serve 4 outputs
            float skv = sv[k];
            float dkv = dv[k];
            float ss  = skv * skv;
            float dd  = dkv * dkv;
            #pragma unroll
            for (int o = 0; o < 4; o++) {
                int t = k - o;
                if (t >= 0 && t < WS) {      // compile-time resolved
                    float w = gw(t);         // literal -> FFMA-imm (rt=1)
                    aMs[o] = fmaf(w, skv, aMs[o]);
                    aMd[o] = fmaf(w, dkv, aMd[o]);
                    aEs[o] = fmaf(w, ss,  aEs[o]);
                    aEd[o] = fmaf(w, dd,  aEd[o]);
                }
            }
        }
        float4* m = s_mid + row * MID_W + cq;
        #pragma unroll
        for (int o = 0; o < 4; o++)
            m[o] = make_float4(aMs[o], aMd[o], aEs[o], aEd[o]);  // STS.128
    }
    __syncthreads();

    // ---- Stage 3: vertical conv + SSIM + local sum; 512 strips == NTHREADS ----
    const float C1 = 1.0f;   // (0.01*100)^2
    const float C2 = 9.0f;   // (0.03*100)^2
    float lsum = 0.f;

    {
        int c  = tid & (TILE_W - 1);
        int rq = (tid >> 5) << 2;

        float Ms[4] = {0.f, 0.f, 0.f, 0.f};
        float Md[4] = {0.f, 0.f, 0.f, 0.f};
        float Es[4] = {0.f, 0.f, 0.f, 0.f};
        float Ed[4] = {0.f, 0.f, 0.f, 0.f};

        #pragma unroll
        for (int k = 0; k < WS + 3; k++) {
            float4 v = s_mid[(rq + k) * MID_W + c];   // one LDS.128 per tap
            #pragma unroll
            for (int o = 0; o < 4; o++) {
                int t = k - o;
                if (t >= 0 && t < WS) {
                    float w = gw(t);
                    Ms[o] = fmaf(w, v.x, Ms[o]);
                    Md[o] = fmaf(w, v.y, Md[o]);
                    Es[o] = fmaf(w, v.z, Es[o]);
                    Ed[o] = fmaf(w, v.w, Ed[o]);
                }
            }
        }

        int gc = c0 + c;
        if (gc < OUT_W) {
            #pragma unroll
            for (int o = 0; o < 4; o++) {
                int gr = r0 + rq + o;
                if (gr < OUT_H) {
                    float ms = Ms[o], md = Md[o];
                    float ms2 = ms * ms;
                    float md2 = md * md;
                    float Ps = Es[o] - ms2;     // s1+s2+2*s12
                    float Qd = Ed[o] - md2;     // s1+s2-2*s12
                    float v1 = 0.5f * (Ps - Qd) + C2;      // 2*s12 + C2
                    float v2 = 0.5f * (Ps + Qd) + C2;      // s1+s2 + C2
                    float num = (0.5f * (ms2 - md2) + C1) * v1;  // (2*mu12+C1)*v1
                    float den = (0.5f * (ms2 + md2) + C1) * v2;  // (mu1^2+mu2^2+C1)*v2
                    lsum += __fdividef(num, den);
                }
            }
        }
    }

    // ---- Stage 4: block partial + fused last-block finalize ----
    #pragma unroll
    for (int off = 16; off > 0; off >>= 1)
        lsum += __shfl_down_sync(0xffffffffu, lsum, off);

    int warp = tid >> 5;
    int lane = tid & 31;
    if (lane == 0) s_red[warp] = lsum;
    __syncthreads();
    if (tid == 0) {
        float t = 0.f;
        #pragma unroll
        for (int i = 0; i < NTHREADS / 32; i++) t += s_red[i];
        int bidx = (blockIdx.z * GY + blockIdx.y) * GX + blockIdx.x;
        g_partials[bidx] = t;
        __threadfence();
        unsigned v = atomicAdd(&g_count, 1u);
        s_flag = (v == (unsigned)(NBLOCKS - 1));
    }
    __syncthreads();

    if (s_flag) {
        // deterministic: fixed summation order independent of which block runs this
        float acc = 0.f;
        for (int i = tid; i < NBLOCKS; i += NTHREADS)
            acc += __ldcg(&g_partials[i]);
        #pragma unroll
        for (int off = 16; off > 0; off >>= 1)
            acc += __shfl_down_sync(0xffffffffu, acc, off);
        if (lane == 0) s_red[warp] = acc;
        __syncthreads();
        if (tid == 0) {
            float tt = 0.f;
            #pragma unroll
            for (int i = 0; i < NTHREADS / 32; i++) tt += s_red[i];
            float mean = tt * (1.0f / ((float)BATCH * OUT_H * OUT_W));
            out[0] = (1.0f - mean) * 0.5f;
            g_count = 0;   // reset for next graph replay
        }
    }
}

extern "C" void kernel_launch(void* const* d_in, const int* in_sizes, int n_in,
                              void* d_out, int out_size)
{
    const float* img1 = (const float*)d_in[0];
    const float* img2 = (const float*)d_in[1];
    float* out = (float*)d_out;

    size_t smem_bytes = (size_t)(2 * IN_H * IN_W_PAD) * sizeof(float)
                      + (size_t)(IN_H * MID_W) * sizeof(float4);
    cudaFuncSetAttribute(ssim_tile_kernel,
                         cudaFuncAttributeMaxDynamicSharedMemorySize,
                         (int)smem_bytes);

    dim3 grid(GX, GY, BATCH);
    ssim_tile_kernel<<<grid, NTHREADS, smem_bytes>>>(img1, img2, out);
}